// round 8
// baseline (speedup 1.0000x reference)
#include <cuda_runtime.h>
#include <cuda_bf16.h>

// DiffJPEG per-8x8-block: D @ X @ D^T -> round(./Q)*Q -> D^T @ M @ D
// R8: per-thread double-buffered cp.async pipeline. Each thread grid-strides
// over blocks; while computing block n from smem slot s, the 16B cp.async
// chunks for block n+2G stream into slot s. Loads are therefore in flight
// during compute, raising DRAM duty cycle. XOR chunk swizzle keeps both the
// async writes and LDS.128 reads bank-conflict-free.

using u64 = unsigned long long;

// D[i][j] = c_i * cos((2j+1) i pi / 16), c_0 = sqrt(1/8), else 0.5
__device__ constexpr float DMc[8][8] = {
    { 0.3535533905932738f,  0.3535533905932738f,  0.3535533905932738f,  0.3535533905932738f,
      0.3535533905932738f,  0.3535533905932738f,  0.3535533905932738f,  0.3535533905932738f },
    { 0.4903926402016152f,  0.4157348061512726f,  0.2777851165098011f,  0.0975451610080642f,
     -0.0975451610080642f, -0.2777851165098011f, -0.4157348061512726f, -0.4903926402016152f },
    { 0.4619397662556434f,  0.1913417161825449f, -0.1913417161825449f, -0.4619397662556434f,
     -0.4619397662556434f, -0.1913417161825449f,  0.1913417161825449f,  0.4619397662556434f },
    { 0.4157348061512726f, -0.0975451610080642f, -0.4903926402016152f, -0.2777851165098011f,
      0.2777851165098011f,  0.4903926402016152f,  0.0975451610080642f, -0.4157348061512726f },
    { 0.3535533905932738f, -0.3535533905932738f, -0.3535533905932738f,  0.3535533905932738f,
      0.3535533905932738f, -0.3535533905932738f, -0.3535533905932738f,  0.3535533905932738f },
    { 0.2777851165098011f, -0.4903926402016152f,  0.0975451610080642f,  0.4157348061512726f,
     -0.4157348061512726f, -0.0975451610080642f,  0.4903926402016152f, -0.2777851165098011f },
    { 0.1913417161825449f, -0.4619397662556434f,  0.4619397662556434f, -0.1913417161825449f,
     -0.1913417161825449f,  0.4619397662556434f, -0.4619397662556434f,  0.1913417161825449f },
    { 0.0975451610080642f, -0.2777851165098011f,  0.4157348061512726f, -0.4903926402016152f,
      0.4903926402016152f, -0.4157348061512726f,  0.2777851165098011f, -0.0975451610080642f },
};

// quality=50 -> Q == q_luma exactly.
__device__ constexpr float QMc[8][8] = {
    { 16.f, 11.f, 10.f, 16.f,  24.f,  40.f,  51.f,  61.f },
    { 12.f, 12.f, 14.f, 19.f,  26.f,  58.f,  60.f,  55.f },
    { 14.f, 13.f, 16.f, 24.f,  40.f,  57.f,  69.f,  56.f },
    { 14.f, 17.f, 22.f, 29.f,  51.f,  87.f,  80.f,  62.f },
    { 18.f, 22.f, 37.f, 56.f,  68.f, 109.f, 103.f,  77.f },
    { 24.f, 35.f, 55.f, 64.f,  81.f, 104.f, 113.f,  92.f },
    { 49.f, 64.f, 78.f, 87.f, 103.f, 121.f, 120.f, 101.f },
    { 72.f, 92.f, 95.f, 98.f, 112.f, 100.f, 103.f,  99.f },
};

__device__ __forceinline__ u64 pk(float a, float b) {
    u64 r; asm("mov.b64 %0, {%1, %2};" : "=l"(r) : "f"(a), "f"(b)); return r;
}
__device__ __forceinline__ void unpk(float& a, float& b, u64 v) {
    asm("mov.b64 {%0, %1}, %2;" : "=f"(a), "=f"(b) : "l"(v));
}
__device__ __forceinline__ u64 fma2(u64 a, u64 b, u64 c) {
    u64 d; asm("fma.rn.f32x2 %0, %1, %2, %3;" : "=l"(d) : "l"(a), "l"(b), "l"(c)); return d;
}
__device__ __forceinline__ u64 mul2(u64 a, u64 b) {
    u64 d; asm("mul.rn.f32x2 %0, %1, %2;" : "=l"(d) : "l"(a), "l"(b)); return d;
}
__device__ __forceinline__ u64 add2(u64 a, u64 b) {
    u64 d; asm("add.rn.f32x2 %0, %1, %2;" : "=l"(d) : "l"(a), "l"(b)); return d;
}
__device__ __forceinline__ u64 sub2(u64 a, u64 b, u64 neg1) {
    return fma2(b, neg1, a);   // a - b
}

__device__ __forceinline__ void cp16(unsigned dst, const void* src) {
    asm volatile("cp.async.cg.shared.global [%0], [%1], 16;" :: "r"(dst), "l"(src) : "memory");
}
#define CP_COMMIT() asm volatile("cp.async.commit_group;" ::: "memory")
#define CP_WAIT1()  asm volatile("cp.async.wait_group 1;"  ::: "memory")

// byte-base (in floats) of linear block b in the (32*3, 64, 64, 8, 8) layout
__device__ __forceinline__ size_t block_base(int b) {
    return ((size_t)(b >> 12) << 18) + ((size_t)((b >> 6) & 63) << 12)
         + ((size_t)(b & 63) << 3);
}

// issue 16 swizzled 16B async copies for one block into staging slot
__device__ __forceinline__ void stage_block(unsigned dstbase, const float* src, int tid) {
    #pragma unroll
    for (int c = 0; c < 16; ++c) {
        unsigned dst = dstbase + ((unsigned)((c + tid) & 15) << 4);
        const float* s = src + ((c >> 1) << 9) + ((c & 1) << 2);   // row c/2, half c&1
        cp16(dst, s);
    }
}

__global__ void __launch_bounds__(128)
diffjpeg_kernel(const float* __restrict__ in, float* __restrict__ out, int nblk)
{
    extern __shared__ char smem[];                       // 2 stages x 128 thr x 256B
    const int tid = threadIdx.x;
    const unsigned sb = (unsigned)__cvta_generic_to_shared(smem);
    const unsigned myb0 = sb + (unsigned)tid * 256u;
    const unsigned myb1 = myb0 + 32768u;
    char* const gen0 = smem + (size_t)tid * 256;
    char* const gen1 = gen0 + 32768;

    const int g = blockIdx.x * 128 + tid;
    const int G = gridDim.x * 128;

    const u64 NEG1 = pk(-1.0f, -1.0f);

    // ---- prologue: prefetch blocks g and g+G ------------------------------
    if (g < nblk) stage_block(myb0, in + block_base(g), tid);
    CP_COMMIT();
    if (g + G < nblk) stage_block(myb1, in + block_base(g + G), tid);
    CP_COMMIT();

    int s = 0;
    for (int b = g; b < nblk; b += G, s ^= 1) {
        CP_WAIT1();                                      // slot s ready
        char* const myb   = s ? gen1 : gen0;
        const unsigned mb = s ? myb1 : myb0;

        float* q = out + block_base(b);

        u64 A[8][4];

        // ---- pass 1: A = D @ X (column transform) via row butterfly -------
        #pragma unroll
        for (int pr = 0; pr < 4; ++pr) {
            // row pr = chunks 2pr, 2pr+1 ; row 7-pr = chunks 14-2pr, 15-2pr
            ulonglong2 ta = *reinterpret_cast<const ulonglong2*>(myb + (((2*pr     + tid) & 15) << 4));
            ulonglong2 tb = *reinterpret_cast<const ulonglong2*>(myb + (((2*pr + 1 + tid) & 15) << 4));
            ulonglong2 ba = *reinterpret_cast<const ulonglong2*>(myb + (((14 - 2*pr + tid) & 15) << 4));
            ulonglong2 bb = *reinterpret_cast<const ulonglong2*>(myb + (((15 - 2*pr + tid) & 15) << 4));
            u64 xt[4] = { ta.x, ta.y, tb.x, tb.y };
            u64 xb[4] = { ba.x, ba.y, bb.x, bb.y };
            u64 S[4], Dd[4];
            #pragma unroll
            for (int pp = 0; pp < 4; ++pp) {
                S[pp]  = add2(xt[pp], xb[pp]);
                Dd[pp] = sub2(xt[pp], xb[pp], NEG1);
            }
            #pragma unroll
            for (int u = 0; u < 4; ++u) {
                u64 ce = pk(DMc[2*u][pr],   DMc[2*u][pr]);
                u64 co = pk(DMc[2*u+1][pr], DMc[2*u+1][pr]);
                #pragma unroll
                for (int pp = 0; pp < 4; ++pp) {
                    if (pr == 0) {
                        A[2*u][pp]   = mul2(ce, S[pp]);
                        A[2*u+1][pp] = mul2(co, Dd[pp]);
                    } else {
                        A[2*u][pp]   = fma2(ce, S[pp],  A[2*u][pp]);
                        A[2*u+1][pp] = fma2(co, Dd[pp], A[2*u+1][pp]);
                    }
                }
            }
        }

        // ---- refill this slot with block b+2G (reads above are done) ------
        {
            int nb2 = b + 2 * G;
            if (nb2 < nblk) stage_block(mb, in + block_base(nb2), tid);
            CP_COMMIT();                                 // (possibly empty) group
        }

        // ---- per row i: row-fwd butterfly, quantize, row-inv butterfly ----
        #pragma unroll
        for (int i = 0; i < 8; ++i) {
            float a0,a1,a2,a3,a4,a5,a6,a7;
            unpk(a0, a1, A[i][0]); unpk(a2, a3, A[i][1]);
            unpk(a4, a5, A[i][2]); unpk(a6, a7, A[i][3]);

            u64 sd[4];
            sd[0] = pk(a0 + a7, a0 - a7);
            sd[1] = pk(a1 + a6, a1 - a6);
            sd[2] = pk(a2 + a5, a2 - a5);
            sd[3] = pk(a3 + a4, a3 - a4);

            u64 r[4];
            #pragma unroll
            for (int t = 0; t < 4; ++t) {
                u64 acc = mul2(sd[0], pk(DMc[2*t][0], DMc[2*t+1][0]));
                #pragma unroll
                for (int j = 1; j < 4; ++j)
                    acc = fma2(sd[j], pk(DMc[2*t][j], DMc[2*t+1][j]), acc);
                r[t] = acc;
            }

            float m[8];
            #pragma unroll
            for (int t = 0; t < 4; ++t) {
                u64 sc = mul2(r[t], pk(1.0f / QMc[i][2*t], 1.0f / QMc[i][2*t+1]));
                float s0, s1; unpk(s0, s1, sc);
                m[2*t]   = rintf(s0) * QMc[i][2*t];
                m[2*t+1] = rintf(s1) * QMc[i][2*t+1];
            }

            u64 U01, U23, V01, V23;
            {
                u64 be = pk(m[0], m[0]);
                U01 = mul2(be, pk(DMc[0][0], DMc[0][1]));
                U23 = mul2(be, pk(DMc[0][2], DMc[0][3]));
                u64 bo = pk(m[1], m[1]);
                V01 = mul2(bo, pk(DMc[1][0], DMc[1][1]));
                V23 = mul2(bo, pk(DMc[1][2], DMc[1][3]));
            }
            #pragma unroll
            for (int t = 1; t < 4; ++t) {
                u64 be = pk(m[2*t], m[2*t]);
                U01 = fma2(be, pk(DMc[2*t][0], DMc[2*t][1]), U01);
                U23 = fma2(be, pk(DMc[2*t][2], DMc[2*t][3]), U23);
                u64 bo = pk(m[2*t+1], m[2*t+1]);
                V01 = fma2(bo, pk(DMc[2*t+1][0], DMc[2*t+1][1]), V01);
                V23 = fma2(bo, pk(DMc[2*t+1][2], DMc[2*t+1][3]), V23);
            }
            A[i][0] = add2(U01, V01);            // (P0, P1)
            A[i][1] = add2(U23, V23);            // (P2, P3)
            u64 t76 = sub2(U01, V01, NEG1);      // (P7, P6)
            u64 t54 = sub2(U23, V23, NEG1);      // (P5, P4)
            { float x, y; unpk(x, y, t54); A[i][2] = pk(y, x); }
            { float x, y; unpk(x, y, t76); A[i][3] = pk(y, x); }
        }

        // ---- pass 5: out = D^T @ P via butterfly, streamed stores ---------
        #pragma unroll
        for (int i = 0; i < 4; ++i) {
            u64 u[4], v[4];
            {
                u64 ce = pk(DMc[0][i], DMc[0][i]);
                u64 co = pk(DMc[1][i], DMc[1][i]);
                #pragma unroll
                for (int pp = 0; pp < 4; ++pp) {
                    u[pp] = mul2(ce, A[0][pp]);
                    v[pp] = mul2(co, A[1][pp]);
                }
            }
            #pragma unroll
            for (int t = 1; t < 4; ++t) {
                u64 ce = pk(DMc[2*t][i], DMc[2*t][i]);
                u64 co = pk(DMc[2*t+1][i], DMc[2*t+1][i]);
                #pragma unroll
                for (int pp = 0; pp < 4; ++pp) {
                    u[pp] = fma2(ce, A[2*t][pp], u[pp]);
                    v[pp] = fma2(co, A[2*t+1][pp], v[pp]);
                }
            }
            ulonglong2* ot = reinterpret_cast<ulonglong2*>(q + (size_t)i * 512);
            ulonglong2* ob = reinterpret_cast<ulonglong2*>(q + (size_t)(7 - i) * 512);
            __stcs(ot,     make_ulonglong2(add2(u[0], v[0]), add2(u[1], v[1])));
            __stcs(ot + 1, make_ulonglong2(add2(u[2], v[2]), add2(u[3], v[3])));
            __stcs(ob,     make_ulonglong2(sub2(u[0], v[0], NEG1), sub2(u[1], v[1], NEG1)));
            __stcs(ob + 1, make_ulonglong2(sub2(u[2], v[2], NEG1), sub2(u[3], v[3], NEG1)));
        }
    }
}

extern "C" void kernel_launch(void* const* d_in, const int* in_sizes, int n_in,
                              void* d_out, int out_size)
{
    const float* in  = (const float*)d_in[0];
    float*       out = (float*)d_out;
    int nblk = in_sizes[0] / 64;                 // number of 8x8 blocks

    constexpr int SMEM = 2 * 128 * 256;          // 64 KB: 2 stages x 128 thr x 256B
    cudaFuncSetAttribute(diffjpeg_kernel,
                         cudaFuncAttributeMaxDynamicSharedMemorySize, SMEM);

    int grid = 444;                              // 3 CTAs/SM x 148 SMs
    diffjpeg_kernel<<<grid, 128, SMEM>>>(in, out, nblk);
}

// round 9
// speedup vs baseline: 1.3369x; 1.3369x over previous
#include <cuda_runtime.h>
#include <cuda_bf16.h>

// DiffJPEG per-8x8-block: D @ X @ D^T -> round(./Q)*Q -> D^T @ M @ D
// R9: grid-stride persistent threads with register double-buffering. Each
// thread prefetches its NEXT block's 16 LDG.128 into a register buffer, then
// computes the CURRENT block (f32x2 butterfly math). Loads are thus in flight
// during ~all of compute, instead of ~25% as in the synchronous version.

using u64 = unsigned long long;

// D[i][j] = c_i * cos((2j+1) i pi / 16), c_0 = sqrt(1/8), else 0.5
__device__ constexpr float DMc[8][8] = {
    { 0.3535533905932738f,  0.3535533905932738f,  0.3535533905932738f,  0.3535533905932738f,
      0.3535533905932738f,  0.3535533905932738f,  0.3535533905932738f,  0.3535533905932738f },
    { 0.4903926402016152f,  0.4157348061512726f,  0.2777851165098011f,  0.0975451610080642f,
     -0.0975451610080642f, -0.2777851165098011f, -0.4157348061512726f, -0.4903926402016152f },
    { 0.4619397662556434f,  0.1913417161825449f, -0.1913417161825449f, -0.4619397662556434f,
     -0.4619397662556434f, -0.1913417161825449f,  0.1913417161825449f,  0.4619397662556434f },
    { 0.4157348061512726f, -0.0975451610080642f, -0.4903926402016152f, -0.2777851165098011f,
      0.2777851165098011f,  0.4903926402016152f,  0.0975451610080642f, -0.4157348061512726f },
    { 0.3535533905932738f, -0.3535533905932738f, -0.3535533905932738f,  0.3535533905932738f,
      0.3535533905932738f, -0.3535533905932738f, -0.3535533905932738f,  0.3535533905932738f },
    { 0.2777851165098011f, -0.4903926402016152f,  0.0975451610080642f,  0.4157348061512726f,
     -0.4157348061512726f, -0.0975451610080642f,  0.4903926402016152f, -0.2777851165098011f },
    { 0.1913417161825449f, -0.4619397662556434f,  0.4619397662556434f, -0.1913417161825449f,
     -0.1913417161825449f,  0.4619397662556434f, -0.4619397662556434f,  0.1913417161825449f },
    { 0.0975451610080642f, -0.2777851165098011f,  0.4157348061512726f, -0.4903926402016152f,
      0.4903926402016152f, -0.4157348061512726f,  0.2777851165098011f, -0.0975451610080642f },
};

// quality=50 -> Q == q_luma exactly.
__device__ constexpr float QMc[8][8] = {
    { 16.f, 11.f, 10.f, 16.f,  24.f,  40.f,  51.f,  61.f },
    { 12.f, 12.f, 14.f, 19.f,  26.f,  58.f,  60.f,  55.f },
    { 14.f, 13.f, 16.f, 24.f,  40.f,  57.f,  69.f,  56.f },
    { 14.f, 17.f, 22.f, 29.f,  51.f,  87.f,  80.f,  62.f },
    { 18.f, 22.f, 37.f, 56.f,  68.f, 109.f, 103.f,  77.f },
    { 24.f, 35.f, 55.f, 64.f,  81.f, 104.f, 113.f,  92.f },
    { 49.f, 64.f, 78.f, 87.f, 103.f, 121.f, 120.f, 101.f },
    { 72.f, 92.f, 95.f, 98.f, 112.f, 100.f, 103.f,  99.f },
};

__device__ __forceinline__ u64 pk(float a, float b) {
    u64 r; asm("mov.b64 %0, {%1, %2};" : "=l"(r) : "f"(a), "f"(b)); return r;
}
__device__ __forceinline__ void unpk(float& a, float& b, u64 v) {
    asm("mov.b64 {%0, %1}, %2;" : "=f"(a), "=f"(b) : "l"(v));
}
__device__ __forceinline__ u64 fma2(u64 a, u64 b, u64 c) {
    u64 d; asm("fma.rn.f32x2 %0, %1, %2, %3;" : "=l"(d) : "l"(a), "l"(b), "l"(c)); return d;
}
__device__ __forceinline__ u64 mul2(u64 a, u64 b) {
    u64 d; asm("mul.rn.f32x2 %0, %1, %2;" : "=l"(d) : "l"(a), "l"(b)); return d;
}
__device__ __forceinline__ u64 add2(u64 a, u64 b) {
    u64 d; asm("add.rn.f32x2 %0, %1, %2;" : "=l"(d) : "l"(a), "l"(b)); return d;
}
__device__ __forceinline__ u64 sub2(u64 a, u64 b, u64 neg1) {
    return fma2(b, neg1, a);   // a - b
}

// float base offset of linear block b in the (96, 64, 64, 8, 8) layout
__device__ __forceinline__ size_t block_base(int b) {
    return ((size_t)(b >> 12) << 18) + ((size_t)((b >> 6) & 63) << 12)
         + ((size_t)(b & 63) << 3);
}

// load 16x16B of one 8x8 block into a register buffer (streaming)
__device__ __forceinline__ void load_block(ulonglong2 (&X)[16], const float* p) {
    #pragma unroll
    for (int k = 0; k < 8; ++k) {
        const ulonglong2* rp = reinterpret_cast<const ulonglong2*>(p + (size_t)k * 512);
        X[2*k]   = __ldcs(rp);
        X[2*k+1] = __ldcs(rp + 1);
    }
}

// full per-block transform from register buffer X, stores to q
__device__ __forceinline__ void process_block(const ulonglong2 (&X)[16],
                                              float* q, u64 NEG1) {
    u64 A[8][4];

    // ---- pass 1: A = D @ Xblk (column transform) via row butterfly -------
    #pragma unroll
    for (int pr = 0; pr < 4; ++pr) {
        u64 xt[4] = { X[2*pr].x,      X[2*pr].y,      X[2*pr+1].x,    X[2*pr+1].y };
        u64 xb[4] = { X[14-2*pr].x,   X[14-2*pr].y,   X[15-2*pr].x,   X[15-2*pr].y };
        u64 S[4], Dd[4];
        #pragma unroll
        for (int pp = 0; pp < 4; ++pp) {
            S[pp]  = add2(xt[pp], xb[pp]);
            Dd[pp] = sub2(xt[pp], xb[pp], NEG1);
        }
        #pragma unroll
        for (int u = 0; u < 4; ++u) {
            u64 ce = pk(DMc[2*u][pr],   DMc[2*u][pr]);
            u64 co = pk(DMc[2*u+1][pr], DMc[2*u+1][pr]);
            #pragma unroll
            for (int pp = 0; pp < 4; ++pp) {
                if (pr == 0) {
                    A[2*u][pp]   = mul2(ce, S[pp]);
                    A[2*u+1][pp] = mul2(co, Dd[pp]);
                } else {
                    A[2*u][pp]   = fma2(ce, S[pp],  A[2*u][pp]);
                    A[2*u+1][pp] = fma2(co, Dd[pp], A[2*u+1][pp]);
                }
            }
        }
    }

    // ---- per row i: row-fwd butterfly, quantize, row-inv butterfly --------
    #pragma unroll
    for (int i = 0; i < 8; ++i) {
        float a0,a1,a2,a3,a4,a5,a6,a7;
        unpk(a0, a1, A[i][0]); unpk(a2, a3, A[i][1]);
        unpk(a4, a5, A[i][2]); unpk(a6, a7, A[i][3]);

        u64 sd[4];
        sd[0] = pk(a0 + a7, a0 - a7);
        sd[1] = pk(a1 + a6, a1 - a6);
        sd[2] = pk(a2 + a5, a2 - a5);
        sd[3] = pk(a3 + a4, a3 - a4);

        u64 r[4];
        #pragma unroll
        for (int t = 0; t < 4; ++t) {
            u64 acc = mul2(sd[0], pk(DMc[2*t][0], DMc[2*t+1][0]));
            #pragma unroll
            for (int j = 1; j < 4; ++j)
                acc = fma2(sd[j], pk(DMc[2*t][j], DMc[2*t+1][j]), acc);
            r[t] = acc;
        }

        float m[8];
        #pragma unroll
        for (int t = 0; t < 4; ++t) {
            u64 sc = mul2(r[t], pk(1.0f / QMc[i][2*t], 1.0f / QMc[i][2*t+1]));
            float s0, s1; unpk(s0, s1, sc);
            m[2*t]   = rintf(s0) * QMc[i][2*t];
            m[2*t+1] = rintf(s1) * QMc[i][2*t+1];
        }

        u64 U01, U23, V01, V23;
        {
            u64 be = pk(m[0], m[0]);
            U01 = mul2(be, pk(DMc[0][0], DMc[0][1]));
            U23 = mul2(be, pk(DMc[0][2], DMc[0][3]));
            u64 bo = pk(m[1], m[1]);
            V01 = mul2(bo, pk(DMc[1][0], DMc[1][1]));
            V23 = mul2(bo, pk(DMc[1][2], DMc[1][3]));
        }
        #pragma unroll
        for (int t = 1; t < 4; ++t) {
            u64 be = pk(m[2*t], m[2*t]);
            U01 = fma2(be, pk(DMc[2*t][0], DMc[2*t][1]), U01);
            U23 = fma2(be, pk(DMc[2*t][2], DMc[2*t][3]), U23);
            u64 bo = pk(m[2*t+1], m[2*t+1]);
            V01 = fma2(bo, pk(DMc[2*t+1][0], DMc[2*t+1][1]), V01);
            V23 = fma2(bo, pk(DMc[2*t+1][2], DMc[2*t+1][3]), V23);
        }
        A[i][0] = add2(U01, V01);            // (P0, P1)
        A[i][1] = add2(U23, V23);            // (P2, P3)
        u64 t76 = sub2(U01, V01, NEG1);      // (P7, P6)
        u64 t54 = sub2(U23, V23, NEG1);      // (P5, P4)
        { float x, y; unpk(x, y, t54); A[i][2] = pk(y, x); }
        { float x, y; unpk(x, y, t76); A[i][3] = pk(y, x); }
    }

    // ---- pass 5: out = D^T @ P via butterfly, streamed stores -------------
    #pragma unroll
    for (int i = 0; i < 4; ++i) {
        u64 u[4], v[4];
        {
            u64 ce = pk(DMc[0][i], DMc[0][i]);
            u64 co = pk(DMc[1][i], DMc[1][i]);
            #pragma unroll
            for (int pp = 0; pp < 4; ++pp) {
                u[pp] = mul2(ce, A[0][pp]);
                v[pp] = mul2(co, A[1][pp]);
            }
        }
        #pragma unroll
        for (int t = 1; t < 4; ++t) {
            u64 ce = pk(DMc[2*t][i], DMc[2*t][i]);
            u64 co = pk(DMc[2*t+1][i], DMc[2*t+1][i]);
            #pragma unroll
            for (int pp = 0; pp < 4; ++pp) {
                u[pp] = fma2(ce, A[2*t][pp], u[pp]);
                v[pp] = fma2(co, A[2*t+1][pp], v[pp]);
            }
        }
        ulonglong2* ot = reinterpret_cast<ulonglong2*>(q + (size_t)i * 512);
        ulonglong2* ob = reinterpret_cast<ulonglong2*>(q + (size_t)(7 - i) * 512);
        __stcs(ot,     make_ulonglong2(add2(u[0], v[0]), add2(u[1], v[1])));
        __stcs(ot + 1, make_ulonglong2(add2(u[2], v[2]), add2(u[3], v[3])));
        __stcs(ob,     make_ulonglong2(sub2(u[0], v[0], NEG1), sub2(u[1], v[1], NEG1)));
        __stcs(ob + 1, make_ulonglong2(sub2(u[2], v[2], NEG1), sub2(u[3], v[3], NEG1)));
    }
}

__global__ void __launch_bounds__(128, 2)
diffjpeg_kernel(const float* __restrict__ in, float* __restrict__ out, int nblk)
{
    const int g = blockIdx.x * 128 + threadIdx.x;
    const int G = gridDim.x * 128;
    const u64 NEG1 = pk(-1.0f, -1.0f);

    if (g >= nblk) return;

    ulonglong2 B0[16], B1[16];

    // prologue: current block into B0
    load_block(B0, in + block_base(g));

    int b = g;
    for (;;) {
        // --- compute from B0, prefetch b+G into B1 first -------------------
        {
            int nb = b + G;
            if (nb < nblk) load_block(B1, in + block_base(nb));
            process_block(B0, out + block_base(b), NEG1);
            b = nb;
            if (b >= nblk) break;
        }
        // --- compute from B1, prefetch b+G into B0 first -------------------
        {
            int nb = b + G;
            if (nb < nblk) load_block(B0, in + block_base(nb));
            process_block(B1, out + block_base(b), NEG1);
            b = nb;
            if (b >= nblk) break;
        }
    }
}

extern "C" void kernel_launch(void* const* d_in, const int* in_sizes, int n_in,
                              void* d_out, int out_size)
{
    const float* in  = (const float*)d_in[0];
    float*       out = (float*)d_out;
    int nblk = in_sizes[0] / 64;                 // number of 8x8 blocks

    int grid = 296;                              // 2 CTAs/SM x 148 SMs
    int maxg = (nblk + 127) / 128;
    if (grid > maxg) grid = maxg;
    diffjpeg_kernel<<<grid, 128>>>(in, out, nblk);
}

// round 10
// speedup vs baseline: 1.4485x; 1.0835x over previous
#include <cuda_runtime.h>
#include <cuda_bf16.h>

// DiffJPEG per-8x8-block: D @ X @ D^T -> round(./Q)*Q -> D^T @ M @ D
// One thread per block, f32x2 packed math + even/odd butterfly decomposition.
// R10: best-known R5 structure (lb(256,3), 24 warps/SM) + fully-packed
// magic-number rounding in the quant step (no FRND, no scalar re-scale) +
// streaming cache hints (single-touch data).

using u64 = unsigned long long;

// D[i][j] = c_i * cos((2j+1) i pi / 16), c_0 = sqrt(1/8), else 0.5
__device__ constexpr float DMc[8][8] = {
    { 0.3535533905932738f,  0.3535533905932738f,  0.3535533905932738f,  0.3535533905932738f,
      0.3535533905932738f,  0.3535533905932738f,  0.3535533905932738f,  0.3535533905932738f },
    { 0.4903926402016152f,  0.4157348061512726f,  0.2777851165098011f,  0.0975451610080642f,
     -0.0975451610080642f, -0.2777851165098011f, -0.4157348061512726f, -0.4903926402016152f },
    { 0.4619397662556434f,  0.1913417161825449f, -0.1913417161825449f, -0.4619397662556434f,
     -0.4619397662556434f, -0.1913417161825449f,  0.1913417161825449f,  0.4619397662556434f },
    { 0.4157348061512726f, -0.0975451610080642f, -0.4903926402016152f, -0.2777851165098011f,
      0.2777851165098011f,  0.4903926402016152f,  0.0975451610080642f, -0.4157348061512726f },
    { 0.3535533905932738f, -0.3535533905932738f, -0.3535533905932738f,  0.3535533905932738f,
      0.3535533905932738f, -0.3535533905932738f, -0.3535533905932738f,  0.3535533905932738f },
    { 0.2777851165098011f, -0.4903926402016152f,  0.0975451610080642f,  0.4157348061512726f,
     -0.4157348061512726f, -0.0975451610080642f,  0.4903926402016152f, -0.2777851165098011f },
    { 0.1913417161825449f, -0.4619397662556434f,  0.4619397662556434f, -0.1913417161825449f,
     -0.1913417161825449f,  0.4619397662556434f, -0.4619397662556434f,  0.1913417161825449f },
    { 0.0975451610080642f, -0.2777851165098011f,  0.4157348061512726f, -0.4903926402016152f,
      0.4903926402016152f, -0.4157348061512726f,  0.2777851165098011f, -0.0975451610080642f },
};

// quality=50 -> Q == q_luma exactly.
__device__ constexpr float QMc[8][8] = {
    { 16.f, 11.f, 10.f, 16.f,  24.f,  40.f,  51.f,  61.f },
    { 12.f, 12.f, 14.f, 19.f,  26.f,  58.f,  60.f,  55.f },
    { 14.f, 13.f, 16.f, 24.f,  40.f,  57.f,  69.f,  56.f },
    { 14.f, 17.f, 22.f, 29.f,  51.f,  87.f,  80.f,  62.f },
    { 18.f, 22.f, 37.f, 56.f,  68.f, 109.f, 103.f,  77.f },
    { 24.f, 35.f, 55.f, 64.f,  81.f, 104.f, 113.f,  92.f },
    { 49.f, 64.f, 78.f, 87.f, 103.f, 121.f, 120.f, 101.f },
    { 72.f, 92.f, 95.f, 98.f, 112.f, 100.f, 103.f,  99.f },
};

__device__ __forceinline__ u64 pk(float a, float b) {
    u64 r; asm("mov.b64 %0, {%1, %2};" : "=l"(r) : "f"(a), "f"(b)); return r;
}
__device__ __forceinline__ void unpk(float& a, float& b, u64 v) {
    asm("mov.b64 {%0, %1}, %2;" : "=f"(a), "=f"(b) : "l"(v));
}
__device__ __forceinline__ u64 fma2(u64 a, u64 b, u64 c) {
    u64 d; asm("fma.rn.f32x2 %0, %1, %2, %3;" : "=l"(d) : "l"(a), "l"(b), "l"(c)); return d;
}
__device__ __forceinline__ u64 mul2(u64 a, u64 b) {
    u64 d; asm("mul.rn.f32x2 %0, %1, %2;" : "=l"(d) : "l"(a), "l"(b)); return d;
}
__device__ __forceinline__ u64 add2(u64 a, u64 b) {
    u64 d; asm("add.rn.f32x2 %0, %1, %2;" : "=l"(d) : "l"(a), "l"(b)); return d;
}
__device__ __forceinline__ u64 sub2(u64 a, u64 b, u64 neg1) {
    return fma2(b, neg1, a);   // a - b  (exact when difference is representable)
}

__global__ void __launch_bounds__(256, 3)
diffjpeg_kernel(const float* __restrict__ in, float* __restrict__ out, int nblk)
{
    int tid = blockIdx.x * 256 + threadIdx.x;
    if (tid >= nblk) return;

    const u64 NEG1   = pk(-1.0f, -1.0f);
    const u64 MAGIC2 = pk(12582912.0f, 12582912.0f);   // 1.5 * 2^23

    int bw  = tid & 63;           // block col (64 per row)
    int t1  = tid >> 6;
    int bh  = t1 & 63;            // block row
    int img = t1 >> 6;            // fused (B,C) plane

    size_t base = ((size_t)img << 18) + ((size_t)bh << 12) + ((size_t)bw << 3);
    const float* p = in  + base;
    float*       q = out + base;

    u64 A[8][4];   // 8 rows x 4 packed j-pairs

    // ---- pass 1: A = D @ X (column transform) via row butterfly ----------
    // Accumulate per butterfly pair t so only one (S_t, D_t) set is live.
    #pragma unroll
    for (int t = 0; t < 4; ++t) {
        const ulonglong2* rt = reinterpret_cast<const ulonglong2*>(p + (size_t)t * 512);
        const ulonglong2* rb = reinterpret_cast<const ulonglong2*>(p + (size_t)(7 - t) * 512);
        ulonglong2 ta = __ldcs(rt), tb = __ldcs(rt + 1);
        ulonglong2 ba = __ldcs(rb), bb = __ldcs(rb + 1);
        u64 xt[4] = { ta.x, ta.y, tb.x, tb.y };
        u64 xb[4] = { ba.x, ba.y, bb.x, bb.y };
        u64 S[4], Dd[4];
        #pragma unroll
        for (int pp = 0; pp < 4; ++pp) {
            S[pp]  = add2(xt[pp], xb[pp]);
            Dd[pp] = sub2(xt[pp], xb[pp], NEG1);
        }
        #pragma unroll
        for (int u = 0; u < 4; ++u) {
            u64 ce = pk(DMc[2*u][t],   DMc[2*u][t]);     // even rows use S
            u64 co = pk(DMc[2*u+1][t], DMc[2*u+1][t]);   // odd rows use Dd
            #pragma unroll
            for (int pp = 0; pp < 4; ++pp) {
                if (t == 0) {
                    A[2*u][pp]   = mul2(ce, S[pp]);
                    A[2*u+1][pp] = mul2(co, Dd[pp]);
                } else {
                    A[2*u][pp]   = fma2(ce, S[pp],  A[2*u][pp]);
                    A[2*u+1][pp] = fma2(co, Dd[pp], A[2*u+1][pp]);
                }
            }
        }
    }

    // ---- per row i: row-fwd butterfly, packed quantize, row-inv butterfly --
    #pragma unroll
    for (int i = 0; i < 8; ++i) {
        float a0,a1,a2,a3,a4,a5,a6,a7;
        unpk(a0, a1, A[i][0]); unpk(a2, a3, A[i][1]);
        unpk(a4, a5, A[i][2]); unpk(a6, a7, A[i][3]);

        // sd[j] = (a[j]+a[7-j], a[j]-a[7-j])
        u64 sd[4];
        sd[0] = pk(a0 + a7, a0 - a7);
        sd[1] = pk(a1 + a6, a1 - a6);
        sd[2] = pk(a2 + a5, a2 - a5);
        sd[3] = pk(a3 + a4, a3 - a4);

        // r[t] = (dct[2t], dct[2t+1]) = sum_j sd[j] * (D[2t][j], D[2t+1][j])
        u64 r[4];
        #pragma unroll
        for (int t = 0; t < 4; ++t) {
            u64 acc = mul2(sd[0], pk(DMc[2*t][0], DMc[2*t+1][0]));
            #pragma unroll
            for (int j = 1; j < 4; ++j)
                acc = fma2(sd[j], pk(DMc[2*t][j], DMc[2*t+1][j]), acc);
            r[t] = acc;
        }

        // packed quant/dequant: round-to-nearest-even via magic constant.
        // |scaled| < 1 << 2^22, so (x + 1.5*2^23) - 1.5*2^23 == rint(x) exactly.
        float m[8];
        #pragma unroll
        for (int t = 0; t < 4; ++t) {
            u64 sc = mul2(r[t], pk(1.0f / QMc[i][2*t], 1.0f / QMc[i][2*t+1]));
            u64 rr = add2(sc, MAGIC2);
            rr = sub2(rr, MAGIC2, NEG1);
            u64 mq = mul2(rr, pk(QMc[i][2*t], QMc[i][2*t+1]));
            unpk(m[2*t], m[2*t+1], mq);
        }

        // row-inv: u[c] = sum_t m[2t]*D[2t][c] ; v[c] = sum_t m[2t+1]*D[2t+1][c]
        // P[c] = u+v, P[7-c] = u-v   (c = 0..3)
        u64 U01, U23, V01, V23;
        {
            u64 be = pk(m[0], m[0]);
            U01 = mul2(be, pk(DMc[0][0], DMc[0][1]));
            U23 = mul2(be, pk(DMc[0][2], DMc[0][3]));
            u64 bo = pk(m[1], m[1]);
            V01 = mul2(bo, pk(DMc[1][0], DMc[1][1]));
            V23 = mul2(bo, pk(DMc[1][2], DMc[1][3]));
        }
        #pragma unroll
        for (int t = 1; t < 4; ++t) {
            u64 be = pk(m[2*t], m[2*t]);
            U01 = fma2(be, pk(DMc[2*t][0], DMc[2*t][1]), U01);
            U23 = fma2(be, pk(DMc[2*t][2], DMc[2*t][3]), U23);
            u64 bo = pk(m[2*t+1], m[2*t+1]);
            V01 = fma2(bo, pk(DMc[2*t+1][0], DMc[2*t+1][1]), V01);
            V23 = fma2(bo, pk(DMc[2*t+1][2], DMc[2*t+1][3]), V23);
        }
        A[i][0] = add2(U01, V01);            // (P0, P1)
        A[i][1] = add2(U23, V23);            // (P2, P3)
        u64 t76 = sub2(U01, V01, NEG1);      // (P7, P6)
        u64 t54 = sub2(U23, V23, NEG1);      // (P5, P4)
        { float x, y; unpk(x, y, t54); A[i][2] = pk(y, x); }  // (P4, P5)
        { float x, y; unpk(x, y, t76); A[i][3] = pk(y, x); }  // (P6, P7)
    }

    // ---- pass 5: out = D^T @ P (column transform) via butterfly ----------
    // out[i] = u_i + v_i, out[7-i] = u_i - v_i
    #pragma unroll
    for (int i = 0; i < 4; ++i) {
        u64 u[4], v[4];
        {
            u64 ce = pk(DMc[0][i], DMc[0][i]);
            u64 co = pk(DMc[1][i], DMc[1][i]);
            #pragma unroll
            for (int pp = 0; pp < 4; ++pp) {
                u[pp] = mul2(ce, A[0][pp]);
                v[pp] = mul2(co, A[1][pp]);
            }
        }
        #pragma unroll
        for (int t = 1; t < 4; ++t) {
            u64 ce = pk(DMc[2*t][i], DMc[2*t][i]);
            u64 co = pk(DMc[2*t+1][i], DMc[2*t+1][i]);
            #pragma unroll
            for (int pp = 0; pp < 4; ++pp) {
                u[pp] = fma2(ce, A[2*t][pp], u[pp]);
                v[pp] = fma2(co, A[2*t+1][pp], v[pp]);
            }
        }
        ulonglong2* ot = reinterpret_cast<ulonglong2*>(q + (size_t)i * 512);
        ulonglong2* ob = reinterpret_cast<ulonglong2*>(q + (size_t)(7 - i) * 512);
        __stcs(ot,     make_ulonglong2(add2(u[0], v[0]), add2(u[1], v[1])));
        __stcs(ot + 1, make_ulonglong2(add2(u[2], v[2]), add2(u[3], v[3])));
        __stcs(ob,     make_ulonglong2(sub2(u[0], v[0], NEG1), sub2(u[1], v[1], NEG1)));
        __stcs(ob + 1, make_ulonglong2(sub2(u[2], v[2], NEG1), sub2(u[3], v[3], NEG1)));
    }
}

extern "C" void kernel_launch(void* const* d_in, const int* in_sizes, int n_in,
                              void* d_out, int out_size)
{
    const float* in  = (const float*)d_in[0];
    float*       out = (float*)d_out;
    int nblk = in_sizes[0] / 64;                 // number of 8x8 blocks
    int grid = (nblk + 255) / 256;
    diffjpeg_kernel<<<grid, 256>>>(in, out, nblk);
}

// round 12
// speedup vs baseline: 1.6790x; 1.1591x over previous
#include <cuda_runtime.h>
#include <cuda_bf16.h>

// DiffJPEG per-8x8-block: D @ X @ D^T -> round(./Q)*Q -> D^T @ M @ D
// R11 (resubmit; previous run died to container infra failure):
// TWO threads per block (lane pair t, t^1). Each thread owns 4 columns.
// Column passes are local; the row phase runs on 4 full rows after a
// shfl.xor(1) exchange (col-split -> row-split), then exchanges back.
// Halves every per-thread dependency chain and doubles blocks in flight
// per warp at unchanged occupancy. f32x2 packed math + butterfly + magic
// rounding, all proven bit-stable (rel_err 0.0 since R3).

using u64 = unsigned long long;

// D[i][j] = c_i * cos((2j+1) i pi / 16), c_0 = sqrt(1/8), else 0.5
__device__ constexpr float DMc[8][8] = {
    { 0.3535533905932738f,  0.3535533905932738f,  0.3535533905932738f,  0.3535533905932738f,
      0.3535533905932738f,  0.3535533905932738f,  0.3535533905932738f,  0.3535533905932738f },
    { 0.4903926402016152f,  0.4157348061512726f,  0.2777851165098011f,  0.0975451610080642f,
     -0.0975451610080642f, -0.2777851165098011f, -0.4157348061512726f, -0.4903926402016152f },
    { 0.4619397662556434f,  0.1913417161825449f, -0.1913417161825449f, -0.4619397662556434f,
     -0.4619397662556434f, -0.1913417161825449f,  0.1913417161825449f,  0.4619397662556434f },
    { 0.4157348061512726f, -0.0975451610080642f, -0.4903926402016152f, -0.2777851165098011f,
      0.2777851165098011f,  0.4903926402016152f,  0.0975451610080642f, -0.4157348061512726f },
    { 0.3535533905932738f, -0.3535533905932738f, -0.3535533905932738f,  0.3535533905932738f,
      0.3535533905932738f, -0.3535533905932738f, -0.3535533905932738f,  0.3535533905932738f },
    { 0.2777851165098011f, -0.4903926402016152f,  0.0975451610080642f,  0.4157348061512726f,
     -0.4157348061512726f, -0.0975451610080642f,  0.4903926402016152f, -0.2777851165098011f },
    { 0.1913417161825449f, -0.4619397662556434f,  0.4619397662556434f, -0.1913417161825449f,
     -0.1913417161825449f,  0.4619397662556434f, -0.4619397662556434f,  0.1913417161825449f },
    { 0.0975451610080642f, -0.2777851165098011f,  0.4157348061512726f, -0.4903926402016152f,
      0.4903926402016152f, -0.4157348061512726f,  0.2777851165098011f, -0.0975451610080642f },
};

// quality=50 -> Q == q_luma exactly.
__device__ constexpr float QMc[8][8] = {
    { 16.f, 11.f, 10.f, 16.f,  24.f,  40.f,  51.f,  61.f },
    { 12.f, 12.f, 14.f, 19.f,  26.f,  58.f,  60.f,  55.f },
    { 14.f, 13.f, 16.f, 24.f,  40.f,  57.f,  69.f,  56.f },
    { 14.f, 17.f, 22.f, 29.f,  51.f,  87.f,  80.f,  62.f },
    { 18.f, 22.f, 37.f, 56.f,  68.f, 109.f, 103.f,  77.f },
    { 24.f, 35.f, 55.f, 64.f,  81.f, 104.f, 113.f,  92.f },
    { 49.f, 64.f, 78.f, 87.f, 103.f, 121.f, 120.f, 101.f },
    { 72.f, 92.f, 95.f, 98.f, 112.f, 100.f, 103.f,  99.f },
};

__device__ __forceinline__ u64 pk(float a, float b) {
    u64 r; asm("mov.b64 %0, {%1, %2};" : "=l"(r) : "f"(a), "f"(b)); return r;
}
__device__ __forceinline__ void unpk(float& a, float& b, u64 v) {
    asm("mov.b64 {%0, %1}, %2;" : "=f"(a), "=f"(b) : "l"(v));
}
__device__ __forceinline__ u64 fma2(u64 a, u64 b, u64 c) {
    u64 d; asm("fma.rn.f32x2 %0, %1, %2, %3;" : "=l"(d) : "l"(a), "l"(b), "l"(c)); return d;
}
__device__ __forceinline__ u64 mul2(u64 a, u64 b) {
    u64 d; asm("mul.rn.f32x2 %0, %1, %2;" : "=l"(d) : "l"(a), "l"(b)); return d;
}
__device__ __forceinline__ u64 add2(u64 a, u64 b) {
    u64 d; asm("add.rn.f32x2 %0, %1, %2;" : "=l"(d) : "l"(a), "l"(b)); return d;
}
__device__ __forceinline__ u64 sub2(u64 a, u64 b, u64 neg1) {
    return fma2(b, neg1, a);   // a - b
}
// exchange a u64 with lane^1
__device__ __forceinline__ u64 shx1(u64 v) {
    unsigned lo, hi;
    asm("mov.b64 {%0, %1}, %2;" : "=r"(lo), "=r"(hi) : "l"(v));
    lo = __shfl_xor_sync(0xffffffffu, lo, 1);
    hi = __shfl_xor_sync(0xffffffffu, hi, 1);
    u64 r; asm("mov.b64 %0, {%1, %2};" : "=l"(r) : "r"(lo), "r"(hi));
    return r;
}

__global__ void __launch_bounds__(256, 3)
diffjpeg_kernel(const float* __restrict__ in, float* __restrict__ out, int nblk)
{
    const int gt  = blockIdx.x * 256 + threadIdx.x;   // global thread
    const int blk = gt >> 1;                          // 8x8 block index
    const bool h  = (gt & 1) != 0;                    // half: false=cols 0-3, true=cols 4-7
    if (blk >= nblk) return;

    const u64 NEG1   = pk(-1.0f, -1.0f);
    const u64 MAGIC2 = pk(12582912.0f, 12582912.0f);  // 1.5 * 2^23

    int bw  = blk & 63;
    int t1  = blk >> 6;
    int bh  = t1 & 63;
    int img = t1 >> 6;
    size_t base = ((size_t)img << 18) + ((size_t)bh << 12) + ((size_t)bw << 3)
                + (h ? 4u : 0u);                       // column offset of my half
    const float* p = in  + base;
    float*       q = out + base;

    // A[r][pp]: my 4 columns (2 packed pairs) of row r, r = 0..7
    u64 A[8][2];

    // ---- pass 1: column DCT via row butterfly (local to my 4 columns) -----
    #pragma unroll
    for (int t = 0; t < 4; ++t) {
        ulonglong2 xt = __ldcs(reinterpret_cast<const ulonglong2*>(p + (size_t)t * 512));
        ulonglong2 xb = __ldcs(reinterpret_cast<const ulonglong2*>(p + (size_t)(7 - t) * 512));
        u64 S[2]  = { add2(xt.x, xb.x),       add2(xt.y, xb.y) };
        u64 Dd[2] = { sub2(xt.x, xb.x, NEG1), sub2(xt.y, xb.y, NEG1) };
        #pragma unroll
        for (int u = 0; u < 4; ++u) {
            u64 ce = pk(DMc[2*u][t],   DMc[2*u][t]);
            u64 co = pk(DMc[2*u+1][t], DMc[2*u+1][t]);
            #pragma unroll
            for (int pp = 0; pp < 2; ++pp) {
                if (t == 0) {
                    A[2*u][pp]   = mul2(ce, S[pp]);
                    A[2*u+1][pp] = mul2(co, Dd[pp]);
                } else {
                    A[2*u][pp]   = fma2(ce, S[pp],  A[2*u][pp]);
                    A[2*u+1][pp] = fma2(co, Dd[pp], A[2*u+1][pp]);
                }
            }
        }
    }

    // ---- exchange 1: col-split -> row-split -------------------------------
    // After this, R[lr][cp] = global colpair cp (0..3) of global row 4h+lr.
    u64 R[4][4];
    #pragma unroll
    for (int lr = 0; lr < 4; ++lr) {
        #pragma unroll
        for (int pp = 0; pp < 2; ++pp) {
            u64 own  = h ? A[lr + 4][pp] : A[lr][pp];      // my cols, my row
            u64 send = h ? A[lr][pp]     : A[lr + 4][pp];  // my cols, partner's row
            u64 recv = shx1(send);
            R[lr][pp]     = h ? recv : own;                // colpairs 0..1
            R[lr][2 + pp] = h ? own  : recv;               // colpairs 2..3
        }
    }

    // ---- row phase: 4 full rows (global row gi = 4h+lr) -------------------
    #pragma unroll
    for (int lr = 0; lr < 4; ++lr) {
        float a0,a1,a2,a3,a4,a5,a6,a7;
        unpk(a0, a1, R[lr][0]); unpk(a2, a3, R[lr][1]);
        unpk(a4, a5, R[lr][2]); unpk(a6, a7, R[lr][3]);

        u64 sd[4];
        sd[0] = pk(a0 + a7, a0 - a7);
        sd[1] = pk(a1 + a6, a1 - a6);
        sd[2] = pk(a2 + a5, a2 - a5);
        sd[3] = pk(a3 + a4, a3 - a4);

        // row-fwd: independent of row index (DCT coeffs only)
        u64 r[4];
        #pragma unroll
        for (int t = 0; t < 4; ++t) {
            u64 acc = mul2(sd[0], pk(DMc[2*t][0], DMc[2*t+1][0]));
            #pragma unroll
            for (int j = 1; j < 4; ++j)
                acc = fma2(sd[j], pk(DMc[2*t][j], DMc[2*t+1][j]), acc);
            r[t] = acc;
        }

        // quant/dequant: Q row = 4h+lr -> per-lane SEL of packed constants
        float m[8];
        #pragma unroll
        for (int t = 0; t < 4; ++t) {
            u64 qinv = h ? pk(1.0f/QMc[4+lr][2*t], 1.0f/QMc[4+lr][2*t+1])
                         : pk(1.0f/QMc[lr][2*t],   1.0f/QMc[lr][2*t+1]);
            u64 qfwd = h ? pk(QMc[4+lr][2*t], QMc[4+lr][2*t+1])
                         : pk(QMc[lr][2*t],   QMc[lr][2*t+1]);
            u64 sc = mul2(r[t], qinv);
            u64 rr = add2(sc, MAGIC2);
            rr = sub2(rr, MAGIC2, NEG1);
            u64 mq = mul2(rr, qfwd);
            unpk(m[2*t], m[2*t+1], mq);
        }

        // row-inv butterfly (row-index independent)
        u64 U01, U23, V01, V23;
        {
            u64 be = pk(m[0], m[0]);
            U01 = mul2(be, pk(DMc[0][0], DMc[0][1]));
            U23 = mul2(be, pk(DMc[0][2], DMc[0][3]));
            u64 bo = pk(m[1], m[1]);
            V01 = mul2(bo, pk(DMc[1][0], DMc[1][1]));
            V23 = mul2(bo, pk(DMc[1][2], DMc[1][3]));
        }
        #pragma unroll
        for (int t = 1; t < 4; ++t) {
            u64 be = pk(m[2*t], m[2*t]);
            U01 = fma2(be, pk(DMc[2*t][0], DMc[2*t][1]), U01);
            U23 = fma2(be, pk(DMc[2*t][2], DMc[2*t][3]), U23);
            u64 bo = pk(m[2*t+1], m[2*t+1]);
            V01 = fma2(bo, pk(DMc[2*t+1][0], DMc[2*t+1][1]), V01);
            V23 = fma2(bo, pk(DMc[2*t+1][2], DMc[2*t+1][3]), V23);
        }
        R[lr][0] = add2(U01, V01);            // (P0, P1)
        R[lr][1] = add2(U23, V23);            // (P2, P3)
        u64 t76 = sub2(U01, V01, NEG1);       // (P7, P6)
        u64 t54 = sub2(U23, V23, NEG1);       // (P5, P4)
        { float x, y; unpk(x, y, t54); R[lr][2] = pk(y, x); }  // (P4, P5)
        { float x, y; unpk(x, y, t76); R[lr][3] = pk(y, x); }  // (P6, P7)
    }

    // ---- exchange 2: row-split -> col-split -------------------------------
    // B[r][pp] = my colpair (2h+pp) of global row r, r = 0..7
    u64 B[8][2];
    #pragma unroll
    for (int lr = 0; lr < 4; ++lr) {
        #pragma unroll
        for (int pp = 0; pp < 2; ++pp) {
            u64 own  = h ? R[lr][2 + pp] : R[lr][pp];      // my colpairs, my row
            u64 send = h ? R[lr][pp]     : R[lr][2 + pp];  // partner's colpairs, my row
            u64 recv = shx1(send);
            B[lr][pp]     = h ? recv : own;                // rows 0..3
            B[lr + 4][pp] = h ? own  : recv;               // rows 4..7
        }
    }

    // ---- pass 5: inverse column DCT via butterfly (local), streamed stores -
    #pragma unroll
    for (int i = 0; i < 4; ++i) {
        u64 u[2], v[2];
        {
            u64 ce = pk(DMc[0][i], DMc[0][i]);
            u64 co = pk(DMc[1][i], DMc[1][i]);
            #pragma unroll
            for (int pp = 0; pp < 2; ++pp) {
                u[pp] = mul2(ce, B[0][pp]);
                v[pp] = mul2(co, B[1][pp]);
            }
        }
        #pragma unroll
        for (int t = 1; t < 4; ++t) {
            u64 ce = pk(DMc[2*t][i], DMc[2*t][i]);
            u64 co = pk(DMc[2*t+1][i], DMc[2*t+1][i]);
            #pragma unroll
            for (int pp = 0; pp < 2; ++pp) {
                u[pp] = fma2(ce, B[2*t][pp], u[pp]);
                v[pp] = fma2(co, B[2*t+1][pp], v[pp]);
            }
        }
        __stcs(reinterpret_cast<ulonglong2*>(q + (size_t)i * 512),
               make_ulonglong2(add2(u[0], v[0]), add2(u[1], v[1])));
        __stcs(reinterpret_cast<ulonglong2*>(q + (size_t)(7 - i) * 512),
               make_ulonglong2(sub2(u[0], v[0], NEG1), sub2(u[1], v[1], NEG1)));
    }
}

extern "C" void kernel_launch(void* const* d_in, const int* in_sizes, int n_in,
                              void* d_out, int out_size)
{
    const float* in  = (const float*)d_in[0];
    float*       out = (float*)d_out;
    int nblk = in_sizes[0] / 64;                  // number of 8x8 blocks
    int nthr = nblk * 2;                          // two threads per block
    int grid = (nthr + 255) / 256;
    diffjpeg_kernel<<<grid, 256>>>(in, out, nblk);
}